// round 1
// baseline (speedup 1.0000x reference)
#include <cuda_runtime.h>
#include <cstdint>

// Problem constants
#define S_LEN 1024
#define B_SZ  8
#define E_DIM 512
#define H_NUM 8
#define QHD   32
#define PHD   4
#define PDIM  192
#define IN_PROJ 544          // (32+32+4)*8
#define NPE   2047           // 2*S-1
#define NPE_PAD 2048

// ---------------- device scratch (no allocations allowed) ----------------
__device__ float g_Q[B_SZ * H_NUM * S_LEN * QHD];     // [b][h][s][d]   8 MB
__device__ float g_K[B_SZ * H_NUM * QHD * S_LEN];     // [b][h][d][s]   8 MB (transposed)
__device__ float g_P[B_SZ * H_NUM * S_LEN * PHD];     // [b][h][s][p]   1 MB
__device__ float g_peT[H_NUM * PHD * NPE_PAD];        // [h][p][n]      256 KB

// ---------------- kernel 1: pe = pos_emb @ linear_pos_w^T (transposed out) --
// peT[h][p][n] = sum_d pos_emb[n][d] * lpw[h*4+p][d]
__global__ void pe_kernel(const float* __restrict__ pos_emb,
                          const float* __restrict__ lpw) {
    int hp = threadIdx.x;                       // 0..31
    int n  = blockIdx.x * blockDim.y + threadIdx.y;
    if (n >= NPE) return;
    const float4* pe4 = (const float4*)(pos_emb + (size_t)n * PDIM);
    const float4* w4  = (const float4*)(lpw + (size_t)hp * PDIM);
    float acc = 0.f;
    #pragma unroll 8
    for (int d = 0; d < PDIM / 4; d++) {
        float4 a = pe4[d];
        float4 b = w4[d];
        acc += a.x * b.x + a.y * b.y + a.z * b.z + a.w * b.w;
    }
    g_peT[hp * NPE_PAD + n] = acc;              // hp = h*4 + p
}

// ---------------- kernel 2: proj GEMM + scatter into Q/K/P ----------------
// proj[r][o] = sum_e x[r][e] * W[o][e] + bias[o],  r = seq*B + b
#define BM 64
#define BN 64
#define BK 16
__global__ void __launch_bounds__(256) proj_kernel(const float* __restrict__ x,
                                                   const float* __restrict__ w,
                                                   const float* __restrict__ bias) {
    __shared__ float As[BK][68];   // [k][m], 68 pad keeps 16B alignment, avoids conflicts
    __shared__ float Bs[BK][68];   // [k][n]
    const int tid = threadIdx.x;
    const int n0 = blockIdx.x * BN;
    const int m0 = blockIdx.y * BM;
    const int tx = tid & 15, ty = tid >> 4;

    float acc[4][4] = {};

    const int arow = tid >> 2;            // 0..63
    const int acol = (tid & 3) * 4;       // 0,4,8,12
    const int bn   = tid & 63;            // 0..63
    const int bk   = (tid >> 6) * 4;      // 0,4,8,12
    const bool bvalid = (n0 + bn) < IN_PROJ;

    for (int k0 = 0; k0 < E_DIM; k0 += BK) {
        float4 av = *(const float4*)(x + (size_t)(m0 + arow) * E_DIM + k0 + acol);
        As[acol + 0][arow] = av.x;
        As[acol + 1][arow] = av.y;
        As[acol + 2][arow] = av.z;
        As[acol + 3][arow] = av.w;
        float4 bv = make_float4(0.f, 0.f, 0.f, 0.f);
        if (bvalid) bv = *(const float4*)(w + (size_t)(n0 + bn) * E_DIM + k0 + bk);
        Bs[bk + 0][bn] = bv.x;
        Bs[bk + 1][bn] = bv.y;
        Bs[bk + 2][bn] = bv.z;
        Bs[bk + 3][bn] = bv.w;
        __syncthreads();
        #pragma unroll
        for (int kk = 0; kk < BK; kk++) {
            float a[4], bb[4];
            *(float4*)a  = *(const float4*)&As[kk][ty * 4];
            *(float4*)bb = *(const float4*)&Bs[kk][tx * 4];
            #pragma unroll
            for (int rr = 0; rr < 4; rr++)
                #pragma unroll
                for (int cc = 0; cc < 4; cc++)
                    acc[rr][cc] = fmaf(a[rr], bb[cc], acc[rr][cc]);
        }
        __syncthreads();
    }

    // epilogue: add bias, scatter to Q/K/P with layouts the scores kernel wants
    #pragma unroll
    for (int rr = 0; rr < 4; rr++) {
        int m = m0 + ty * 4 + rr;
        int seq = m >> 3;             // row index = seq*B + b
        int b   = m & 7;
        #pragma unroll
        for (int cc = 0; cc < 4; cc++) {
            int o = n0 + tx * 4 + cc;
            if (o >= IN_PROJ) continue;
            float v = acc[rr][cc] + bias[o];
            if (o < 256) {                              // q
                int h = o >> 5, d = o & 31;
                g_Q[(((size_t)(b * H_NUM + h)) * S_LEN + seq) * QHD + d] = v;
            } else if (o < 512) {                       // k (store d-major)
                int oo = o - 256;
                int h = oo >> 5, d = oo & 31;
                g_K[(((size_t)(b * H_NUM + h)) * QHD + d) * S_LEN + seq] = v;
            } else {                                    // p
                int oo = o - 512;
                int h = oo >> 2, d = oo & 3;
                g_P[(((size_t)(b * H_NUM + h)) * S_LEN + seq) * PHD + d] = v;
            }
        }
    }
}

// ---------------- kernel 3: fused scores + rel-shift + mask + softmax -----
// block = (qtile of 32 rows) x b x h ; 256 threads; warp w owns 4 rows,
// lane owns cols j = t*32 + lane, t = 0..31.
#define SC_SMEM_FLOATS (QHD * S_LEN + 32 * QHD + 32 * PHD + PHD * NPE_PAD)
#define SC_SMEM_BYTES  (SC_SMEM_FLOATS * 4 + 1024)

__global__ void __launch_bounds__(256, 1)
scores_kernel(const unsigned char* __restrict__ mask, float* __restrict__ out) {
    extern __shared__ float sm[];
    float* kT = sm;                       // [32][1024]
    float* qs = kT + QHD * S_LEN;         // [32][32]
    float* ps = qs + 32 * QHD;            // [32][4]
    float* pe = ps + 32 * PHD;            // [4][2048]
    unsigned char* msk = (unsigned char*)(pe + PHD * NPE_PAD);  // [1024]

    const int i0 = blockIdx.x * 32;
    const int b  = blockIdx.y;
    const int h  = blockIdx.z;
    const int tid = threadIdx.x;
    const size_t bh = (size_t)(b * H_NUM + h);

    // --- cooperative loads (all coalesced float4) ---
    {
        const float4* kg = (const float4*)(g_K + bh * QHD * S_LEN);
        float4* kd = (float4*)kT;
        #pragma unroll 8
        for (int i = tid; i < QHD * S_LEN / 4; i += 256) kd[i] = kg[i];

        const float4* qg = (const float4*)(g_Q + (bh * S_LEN + i0) * QHD);
        ((float4*)qs)[tid] = qg[tid];                     // 256 * 4 = 1024 floats

        if (tid < 32)
            ((float4*)ps)[tid] = ((const float4*)(g_P + (bh * S_LEN + i0) * PHD))[tid];

        const float4* peg = (const float4*)(g_peT + (size_t)h * PHD * NPE_PAD);
        #pragma unroll 2
        for (int i = tid; i < PHD * NPE_PAD / 4; i += 256) ((float4*)pe)[i] = peg[i];

        ((int*)msk)[tid] = ((const int*)(mask + (size_t)b * S_LEN))[tid];
    }
    __syncthreads();

    const int w = tid >> 5, lane = tid & 31;
    const int r0 = w * 4;

    float s[4][32];
    #pragma unroll
    for (int rr = 0; rr < 4; rr++)
        #pragma unroll
        for (int t = 0; t < 32; t++) s[rr][t] = 0.f;

    // --- QK^T: 4 rows x 32 cols per lane; FMA:LDS = 128:36 ---
    #pragma unroll 4
    for (int d = 0; d < QHD; d++) {
        float q0 = qs[(r0 + 0) * QHD + d];
        float q1 = qs[(r0 + 1) * QHD + d];
        float q2 = qs[(r0 + 2) * QHD + d];
        float q3 = qs[(r0 + 3) * QHD + d];
        const float* kr = kT + d * S_LEN + lane;
        #pragma unroll
        for (int t = 0; t < 32; t++) {
            float kv = kr[t * 32];
            s[0][t] = fmaf(q0, kv, s[0][t]);
            s[1][t] = fmaf(q1, kv, s[1][t]);
            s[2][t] = fmaf(q2, kv, s[2][t]);
            s[3][t] = fmaf(q3, kv, s[3][t]);
        }
    }

    // --- pos scores + mask + softmax + write, per row ---
    #pragma unroll
    for (int rr = 0; rr < 4; rr++) {
        const int i = i0 + r0 + rr;
        const float p0 = ps[(r0 + rr) * PHD + 0];
        const float p1 = ps[(r0 + rr) * PHD + 1];
        const float p2 = ps[(r0 + rr) * PHD + 2];
        const float p3 = ps[(r0 + rr) * PHD + 3];
        const int nb = (S_LEN - 1) - i + lane;     // n = 1023 - i + j
        #pragma unroll
        for (int t = 0; t < 32; t++) {
            int n = nb + t * 32;
            float v = p0 * pe[n];
            v = fmaf(p1, pe[NPE_PAD + n], v);
            v = fmaf(p2, pe[2 * NPE_PAD + n], v);
            v = fmaf(p3, pe[3 * NPE_PAD + n], v);
            float sv = s[rr][t] + v;
            if (msk[t * 32 + lane]) sv = -1000.0f;
            s[rr][t] = sv;
        }
        // softmax over the 1024 cols owned by this warp-row
        float m = s[rr][0];
        #pragma unroll
        for (int t = 1; t < 32; t++) m = fmaxf(m, s[rr][t]);
        #pragma unroll
        for (int off = 16; off > 0; off >>= 1)
            m = fmaxf(m, __shfl_xor_sync(0xffffffffu, m, off));
        float sum = 0.f;
        #pragma unroll
        for (int t = 0; t < 32; t++) {
            float e = __expf(s[rr][t] - m);
            s[rr][t] = e;
            sum += e;
        }
        #pragma unroll
        for (int off = 16; off > 0; off >>= 1)
            sum += __shfl_xor_sync(0xffffffffu, sum, off);
        float inv = 1.0f / sum;
        float* orow = out + ((((size_t)h * B_SZ + b) * S_LEN + i) << 10);
        #pragma unroll
        for (int t = 0; t < 32; t++)
            orow[t * 32 + lane] = s[rr][t] * inv;
    }
}

// ---------------- launch ----------------
extern "C" void kernel_launch(void* const* d_in, const int* in_sizes, int n_in,
                              void* d_out, int out_size) {
    const float* x        = (const float*)d_in[0];
    const float* pos_emb  = (const float*)d_in[1];
    const unsigned char* kpm = (const unsigned char*)d_in[2];
    const float* in_w     = (const float*)d_in[3];
    const float* in_b     = (const float*)d_in[4];
    const float* lpw      = (const float*)d_in[5];
    float* out = (float*)d_out;

    // pe: 2047 rows, 32 (h,p) each
    {
        dim3 blk(32, 8);
        dim3 grd((NPE + 7) / 8);
        pe_kernel<<<grd, blk>>>(pos_emb, lpw);
    }
    // proj GEMM: M=8192, N=544, K=512
    {
        dim3 grd((IN_PROJ + BN - 1) / BN, (S_LEN * B_SZ) / BM);
        proj_kernel<<<grd, 256>>>(x, in_w, in_b);
    }
    // fused scores + softmax
    {
        cudaFuncSetAttribute(scores_kernel,
                             cudaFuncAttributeMaxDynamicSharedMemorySize,
                             SC_SMEM_BYTES);
        dim3 grd(S_LEN / 32, B_SZ, H_NUM);
        scores_kernel<<<grd, 256, SC_SMEM_BYTES>>>(kpm, out);
    }
}